// round 2
// baseline (speedup 1.0000x reference)
#include <cuda_runtime.h>

#define BSZ   64
#define FD    256
#define MD    128
#define NBINS 8
#define NPAIR (BSZ * (BSZ + 1) / 2)   // 2080 unordered pairs
#define KC    8
#define NCHUNK (FD / KC)

// One CTA per (tensor, unordered pair). 256 threads (16x16), each thread owns an
// 8x8 scattered micro-tile of the 128x128 Gram matrix (rows {4ty..4ty+3, 64+4ty..},
// cols {4tx..4tx+3, 64+4tx..}) -> conflict-free float4 LDS.
__global__ __launch_bounds__(256, 2)
void pair_hist_kernel(const float* __restrict__ m1,
                      const float* __restrict__ m2,
                      float* __restrict__ out)
{
    __shared__ float As[2][KC][MD];
    __shared__ float Bs[2][KC][MD];
    __shared__ float s_bins[NBINS - 1];
    __shared__ float s_wmn[8], s_wmx[8];
    __shared__ float s_mn, s_mx;

    const int bid = blockIdx.x;
    const int t   = (bid >= NPAIR) ? 1 : 0;
    int p = bid - t * NPAIR;

    // unrank p -> (a, b) with a <= b
    int a = 0;
    while (p >= BSZ - a) { p -= BSZ - a; a++; }
    const int b = a + p;

    const float* basep = t ? m2 : m1;
    const float* Ag = basep + (size_t)a * FD * MD;
    const float* Bg = basep + (size_t)b * FD * MD;

    const int tid = threadIdx.x;
    const int tx  = tid & 15;
    const int ty  = tid >> 4;
    const int lrow = tid >> 5;         // 0..7   (global-load row within chunk)
    const int lcol = (tid & 31) * 4;   // 0..124 (float4 column)

    if (tid < NBINS - 1) s_bins[tid] = 0.0f;

    float acc[8][8];
#pragma unroll
    for (int i = 0; i < 8; i++)
#pragma unroll
        for (int j = 0; j < 8; j++) acc[i][j] = 0.0f;

    // prologue: chunk 0 -> smem buf 0
    float4 pa = *(const float4*)(Ag + lrow * MD + lcol);
    float4 pb = *(const float4*)(Bg + lrow * MD + lcol);
    *(float4*)&As[0][lrow][lcol] = pa;
    *(float4*)&Bs[0][lrow][lcol] = pb;
    __syncthreads();

    int buf = 0;
    for (int k = 0; k < NCHUNK; k++) {
        if (k + 1 < NCHUNK) {
            const float* Ap = Ag + (size_t)(k + 1) * KC * MD;
            const float* Bp = Bg + (size_t)(k + 1) * KC * MD;
            pa = *(const float4*)(Ap + lrow * MD + lcol);
            pb = *(const float4*)(Bp + lrow * MD + lcol);
        }
#pragma unroll
        for (int f = 0; f < KC; f++) {
            float4 a0 = *(const float4*)&As[buf][f][4 * ty];
            float4 a1 = *(const float4*)&As[buf][f][64 + 4 * ty];
            float4 b0 = *(const float4*)&Bs[buf][f][4 * tx];
            float4 b1 = *(const float4*)&Bs[buf][f][64 + 4 * tx];
            float av[8] = {a0.x, a0.y, a0.z, a0.w, a1.x, a1.y, a1.z, a1.w};
            float bv[8] = {b0.x, b0.y, b0.z, b0.w, b1.x, b1.y, b1.z, b1.w};
#pragma unroll
            for (int i = 0; i < 8; i++)
#pragma unroll
                for (int j = 0; j < 8; j++)
                    acc[i][j] = fmaf(av[i], bv[j], acc[i][j]);
        }
        if (k + 1 < NCHUNK) {
            *(float4*)&As[buf ^ 1][lrow][lcol] = pa;
            *(float4*)&Bs[buf ^ 1][lrow][lcol] = pb;
            __syncthreads();
            buf ^= 1;
        }
    }

    // ---- per-thread min/max over 64 accumulators ----
    float mn = acc[0][0], mx = acc[0][0];
#pragma unroll
    for (int i = 0; i < 8; i++)
#pragma unroll
        for (int j = 0; j < 8; j++) {
            mn = fminf(mn, acc[i][j]);
            mx = fmaxf(mx, acc[i][j]);
        }
    // warp reduce
#pragma unroll
    for (int o = 16; o > 0; o >>= 1) {
        mn = fminf(mn, __shfl_xor_sync(0xffffffffu, mn, o));
        mx = fmaxf(mx, __shfl_xor_sync(0xffffffffu, mx, o));
    }
    const int wid = tid >> 5, lid = tid & 31;
    if (lid == 0) { s_wmn[wid] = mn; s_wmx[wid] = mx; }
    __syncthreads();
    if (tid == 0) {
        float m0 = s_wmn[0], m1v = s_wmx[0];
#pragma unroll
        for (int w = 1; w < 8; w++) {
            m0  = fminf(m0,  s_wmn[w]);
            m1v = fmaxf(m1v, s_wmx[w]);
        }
        s_mn = m0; s_mx = m1v;
    }
    __syncthreads();
    mn = s_mn; mx = s_mx;

    // ---- histogram via cumulative >= counts ----
    // idx = clip(floor((x-mn)/denom*8), 0, 7);  idx >= k  <=>  (x-mn)*scale >= k
    const float denom = (mx > mn) ? (mx - mn) : 1.0f;
    const float scale = 8.0f / denom;
    const float off   = -mn * scale;
    float cge[7] = {0, 0, 0, 0, 0, 0, 0};
#pragma unroll
    for (int i = 0; i < 8; i++)
#pragma unroll
        for (int j = 0; j < 8; j++) {
            float y = fmaf(acc[i][j], scale, off);
#pragma unroll
            for (int q = 0; q < 7; q++)
                cge[q] += (y >= (float)(q + 1)) ? 1.0f : 0.0f;
        }
    // reduce counters: warp shuffle sum, then one shared atomic per warp
#pragma unroll
    for (int q = 0; q < 7; q++) {
#pragma unroll
        for (int o = 16; o > 0; o >>= 1)
            cge[q] += __shfl_xor_sync(0xffffffffu, cge[q], o);
        if (lid == 0) atomicAdd(&s_bins[q], cge[q]);
    }
    __syncthreads();

    if (tid == 0) {
        float C[9];
        C[0] = (float)(MD * MD);   // 16384
        C[8] = 0.0f;
#pragma unroll
        for (int q = 1; q < 8; q++) C[q] = s_bins[q - 1];
        float h[8], nrm = 0.0f;
#pragma unroll
        for (int q = 0; q < 8; q++) {
            h[q] = C[q] - C[q + 1];
            nrm += h[q] * h[q];
        }
        const float inv = 1.0f / sqrtf(nrm);   // nrm >= 16384^2/8, eps irrelevant
        const int r1 = a * BSZ + b;
        const int r2 = b * BSZ + a;
        float* o1 = out + (size_t)r1 * 16 + t * 8;
        float* o2 = out + (size_t)r2 * 16 + t * 8;
#pragma unroll
        for (int q = 0; q < 8; q++) {
            float v = h[q] * inv;
            o1[q] = v;
            o2[q] = v;
        }
    }
}

extern "C" void kernel_launch(void* const* d_in, const int* in_sizes, int n_in,
                              void* d_out, int out_size)
{
    const float* m1 = (const float*)d_in[0];
    const float* m2 = (const float*)d_in[1];
    float* out = (float*)d_out;
    pair_hist_kernel<<<2 * NPAIR, 256>>>(m1, m2, out);
}

// round 4
// speedup vs baseline: 2.1731x; 2.1731x over previous
#include <cuda_runtime.h>
#include <cuda_bf16.h>
#include <cstdint>

#define BSZ   64
#define FD    256
#define MD    128
#define NBINS 8
#define NPAIR (BSZ * (BSZ + 1) / 2)     // 2080
#define KCH   64                        // K elements per SMEM chunk
#define NCHUNK (FD / KCH)               // 4
#define TILE_EL (MD * KCH)              // 8192 bf16 per tile
#define TILE_BYTES (TILE_EL * 2)        // 16384

// Split-precision K-major scratch: [t*64+b][chunk][m][k_local], bf16
__device__ __nv_bfloat16 g_hi[2 * BSZ * NCHUNK * TILE_EL];   // 8 MB
__device__ __nv_bfloat16 g_lo[2 * BSZ * NCHUNK * TILE_EL];   // 8 MB

__device__ __forceinline__ uint32_t smem_u32(const void* p) {
    uint32_t a;
    asm("{ .reg .u64 t; cvta.to.shared.u64 t, %1; cvt.u32.u64 %0, t; }"
        : "=r"(a) : "l"(p));
    return a;
}

#define SWZ(o) ((o) ^ (((o) >> 3) & 0x70))

// ---------------- Kernel 1: fp32 -> bf16 hi/lo split + transpose ----------------
__global__ __launch_bounds__(256)
void split_transpose_kernel(const float* __restrict__ m1,
                            const float* __restrict__ m2)
{
    __shared__ float tile[KCH][MD + 1];
    const int tb = blockIdx.x;              // 0..127 = t*64 + b
    const int t  = tb >> 6;
    const int b  = tb & 63;
    const float* src = (t ? m2 : m1) + (size_t)b * FD * MD;
    const int tid = threadIdx.x;

    for (int kc = 0; kc < NCHUNK; kc++) {
        const float* s = src + (size_t)kc * KCH * MD;
#pragma unroll
        for (int it = 0; it < 8; it++) {
            int i4 = it * 256 + tid;               // 0..2047 float4s
            int f  = i4 >> 5;
            int m4 = (i4 & 31) * 4;
            float4 v = *(const float4*)(s + f * MD + m4);
            tile[f][m4]     = v.x;
            tile[f][m4 + 1] = v.y;
            tile[f][m4 + 2] = v.z;
            tile[f][m4 + 3] = v.w;
        }
        __syncthreads();
        size_t base = ((size_t)tb * NCHUNK + kc) * TILE_EL;
#pragma unroll
        for (int it = 0; it < 4; it++) {
            int idx = it * 256 + tid;              // [128 m][8 kgroups]
            int m  = idx >> 3;
            int kl = (idx & 7) * 8;
            __nv_bfloat16 hv[8], lv[8];
#pragma unroll
            for (int j = 0; j < 8; j++) {
                float x = tile[kl + j][m];
                __nv_bfloat16 h = __float2bfloat16(x);
                hv[j] = h;
                lv[j] = __float2bfloat16(x - __bfloat162float(h));
            }
            *(uint4*)(&g_hi[base + (size_t)m * KCH + kl]) = *(const uint4*)hv;
            *(uint4*)(&g_lo[base + (size_t)m * KCH + kl]) = *(const uint4*)lv;
        }
        __syncthreads();
    }
}

// ---------------- Kernel 2: legacy-HMMA Gram + fused histogram ----------------
// dynamic smem: 4 tiles (Ahi, Alo, Bhi, Blo), 16KB each, swizzled 128B rows
#define SMEM_TOTAL (4 * TILE_BYTES)   // 65536

#define MMA_BF16(d, A, B)                                                      \
    asm volatile("mma.sync.aligned.m16n8k16.row.col.f32.bf16.bf16.f32 "        \
                 "{%0,%1,%2,%3},{%4,%5,%6,%7},{%8,%9},{%0,%1,%2,%3};"          \
                 : "+f"(d[0]), "+f"(d[1]), "+f"(d[2]), "+f"(d[3])              \
                 : "r"(A[0]), "r"(A[1]), "r"(A[2]), "r"(A[3]),                 \
                   "r"(B[0]), "r"(B[1]))

#define LDSM_X4(r, addr)                                                       \
    asm volatile("ldmatrix.sync.aligned.m8n8.x4.shared.b16 {%0,%1,%2,%3},[%4];"\
                 : "=r"(r[0]), "=r"(r[1]), "=r"(r[2]), "=r"(r[3])              \
                 : "r"(addr))

__device__ __forceinline__ void load_chunk(uint32_t sbase,
                                           const __nv_bfloat16* gA_hi,
                                           const __nv_bfloat16* gA_lo,
                                           const __nv_bfloat16* gB_hi,
                                           const __nv_bfloat16* gB_lo,
                                           int tid)
{
    const __nv_bfloat16* gs[4] = { gA_hi, gA_lo, gB_hi, gB_lo };
#pragma unroll
    for (int T = 0; T < 4; T++) {
#pragma unroll
        for (int it = 0; it < 4; it++) {
            int idx = it * 256 + tid;           // 1024 16B-chunks per tile
            int m  = idx >> 3;
            int kg = idx & 7;
            uint32_t soff = (uint32_t)T * TILE_BYTES + SWZ((uint32_t)(m * 128 + kg * 16));
            const void* ga = gs[T] + (size_t)m * KCH + kg * 8;
            asm volatile("cp.async.cg.shared.global [%0], [%1], 16;"
                         :: "r"(sbase + soff), "l"(ga));
        }
    }
    asm volatile("cp.async.commit_group;" ::: "memory");
}

__global__ __launch_bounds__(256, 2)
void pair_hist_mma_kernel(float* __restrict__ out)
{
    extern __shared__ __align__(16) char smem[];
    const uint32_t sb = smem_u32(smem);

    __shared__ float s_bins[NBINS - 1];
    __shared__ float s_wmn[8], s_wmx[8];
    __shared__ float s_mm[2];

    const int tid  = threadIdx.x;
    const int wid  = tid >> 5;
    const int lane = tid & 31;
    const int wm   = wid & 1;     // 2 row-groups of 64
    const int wn   = wid >> 1;    // 4 col-groups of 32

    if (tid < NBINS - 1) s_bins[tid] = 0.0f;

    // unrank pair
    const int bid = blockIdx.x;
    const int t   = (bid >= NPAIR) ? 1 : 0;
    int p = bid - t * NPAIR;
    int a = 0;
    while (p >= BSZ - a) { p -= BSZ - a; a++; }
    const int b = a + p;

    const size_t tA = (size_t)(t * BSZ + a) * NCHUNK * TILE_EL;
    const size_t tB = (size_t)(t * BSZ + b) * NCHUNK * TILE_EL;

    float acc[4][4][4];
#pragma unroll
    for (int i = 0; i < 4; i++)
#pragma unroll
        for (int j = 0; j < 4; j++)
#pragma unroll
            for (int q = 0; q < 4; q++) acc[i][j][q] = 0.0f;

    // precompute ldmatrix shared addresses (constant across chunks/ksteps up to ks*32)
    // A: lanes 0-15 -> rows (m16), lanes>=16 -> +16B k-chunk
    const int a_row  = wm * 64 + (lane & 15);
    const int a_koff = (lane >> 4) * 16;
    // B: lanes 0-7 n0-7 k0 | 8-15 n0-7 k8 | 16-23 n8-15 k0 | 24-31 n8-15 k8
    const int b_row  = wn * 32 + ((lane >> 4) << 3) + (lane & 7);
    const int b_koff = ((lane >> 3) & 1) * 16;

    load_chunk(sb, g_hi + tA, g_lo + tA, g_hi + tB, g_lo + tB, tid);
    asm volatile("cp.async.wait_group 0;" ::: "memory");
    __syncthreads();

    for (int c = 0; c < NCHUNK; c++) {
#pragma unroll
        for (int ks = 0; ks < 4; ks++) {       // 4 k16-steps within KCH=64
            uint32_t ahi[4][4], alo[4][4];
#pragma unroll
            for (int mt = 0; mt < 4; mt++) {
                uint32_t off = SWZ((uint32_t)((a_row + mt * 16) * 128 + ks * 32 + a_koff));
                LDSM_X4(ahi[mt], sb + off);                     // Ahi tile at +0
                LDSM_X4(alo[mt], sb + TILE_BYTES + off);        // Alo tile
            }
            uint32_t bhi[4][2], blo[4][2];
#pragma unroll
            for (int np = 0; np < 2; np++) {
                uint32_t off = SWZ((uint32_t)((b_row + np * 16) * 128 + ks * 32 + b_koff));
                uint32_t rh[4], rl[4];
                LDSM_X4(rh, sb + 2 * TILE_BYTES + off);         // Bhi
                LDSM_X4(rl, sb + 3 * TILE_BYTES + off);         // Blo
                bhi[np * 2][0] = rh[0]; bhi[np * 2][1] = rh[1];
                bhi[np * 2 + 1][0] = rh[2]; bhi[np * 2 + 1][1] = rh[3];
                blo[np * 2][0] = rl[0]; blo[np * 2][1] = rl[1];
                blo[np * 2 + 1][0] = rl[2]; blo[np * 2 + 1][1] = rl[3];
            }
#pragma unroll
            for (int mt = 0; mt < 4; mt++)
#pragma unroll
                for (int nt = 0; nt < 4; nt++) {
                    MMA_BF16(acc[mt][nt], ahi[mt], bhi[nt]);
                    MMA_BF16(acc[mt][nt], ahi[mt], blo[nt]);
                    MMA_BF16(acc[mt][nt], alo[mt], bhi[nt]);
                }
        }
        if (c + 1 < NCHUNK) {
            __syncthreads();                    // everyone done reading smem
            size_t co = (size_t)(c + 1) * TILE_EL;
            load_chunk(sb, g_hi + tA + co, g_lo + tA + co,
                           g_hi + tB + co, g_lo + tB + co, tid);
            asm volatile("cp.async.wait_group 0;" ::: "memory");
            __syncthreads();
        }
    }

    // ---- epilogue: histogram over the 64 per-thread accumulators ----
    float* av = &acc[0][0][0];

    float mn = av[0], mx = av[0];
#pragma unroll
    for (int i = 1; i < 64; i++) {
        mn = fminf(mn, av[i]);
        mx = fmaxf(mx, av[i]);
    }
#pragma unroll
    for (int o = 16; o > 0; o >>= 1) {
        mn = fminf(mn, __shfl_xor_sync(0xffffffffu, mn, o));
        mx = fmaxf(mx, __shfl_xor_sync(0xffffffffu, mx, o));
    }
    if (lane == 0) { s_wmn[wid] = mn; s_wmx[wid] = mx; }
    __syncthreads();
    if (tid == 0) {
        float m0 = s_wmn[0], m1v = s_wmx[0];
#pragma unroll
        for (int w = 1; w < 8; w++) {
            m0  = fminf(m0,  s_wmn[w]);
            m1v = fmaxf(m1v, s_wmx[w]);
        }
        s_mm[0] = m0; s_mm[1] = m1v;
    }
    __syncthreads();
    mn = s_mm[0]; mx = s_mm[1];

    const float denom = (mx > mn) ? (mx - mn) : 1.0f;
    const float scale = 8.0f / denom;
    const float off   = -mn * scale;
    float cge[7] = {0, 0, 0, 0, 0, 0, 0};
#pragma unroll
    for (int i = 0; i < 64; i++) {
        float y = fmaf(av[i], scale, off);
#pragma unroll
        for (int q = 0; q < 7; q++)
            cge[q] += (y >= (float)(q + 1)) ? 1.0f : 0.0f;
    }
#pragma unroll
    for (int q = 0; q < 7; q++) {
#pragma unroll
        for (int o = 16; o > 0; o >>= 1)
            cge[q] += __shfl_xor_sync(0xffffffffu, cge[q], o);
        if (lane == 0) atomicAdd(&s_bins[q], cge[q]);
    }
    __syncthreads();

    if (tid == 0) {
        float C[9];
        C[0] = (float)(MD * MD);
        C[8] = 0.0f;
#pragma unroll
        for (int q = 1; q < 8; q++) C[q] = s_bins[q - 1];
        float h[8], nrm = 0.0f;
#pragma unroll
        for (int q = 0; q < 8; q++) {
            h[q] = C[q] - C[q + 1];
            nrm += h[q] * h[q];
        }
        const float inv = 1.0f / sqrtf(nrm);
        const int r1 = a * BSZ + b;
        const int r2 = b * BSZ + a;
        float* o1 = out + (size_t)r1 * 16 + t * 8;
        float* o2 = out + (size_t)r2 * 16 + t * 8;
#pragma unroll
        for (int q = 0; q < 8; q++) {
            float v = h[q] * inv;
            o1[q] = v;
            o2[q] = v;
        }
    }
}

// ---------------- launch ----------------
extern "C" void kernel_launch(void* const* d_in, const int* in_sizes, int n_in,
                              void* d_out, int out_size)
{
    const float* m1 = (const float*)d_in[0];
    const float* m2 = (const float*)d_in[1];
    float* out = (float*)d_out;

    cudaFuncSetAttribute(pair_hist_mma_kernel,
                         cudaFuncAttributeMaxDynamicSharedMemorySize, SMEM_TOTAL);

    split_transpose_kernel<<<2 * BSZ, 256>>>(m1, m2);
    pair_hist_mma_kernel<<<2 * NPAIR, 256, SMEM_TOTAL>>>(out);
}

// round 6
// speedup vs baseline: 2.9738x; 1.3684x over previous
#include <cuda_runtime.h>
#include <cuda_fp16.h>
#include <cstdint>

#define BSZ   64
#define FD    256
#define MD    128
#define NBINS 8
#define NPAIR (BSZ * (BSZ + 1) / 2)     // 2080
#define KCH   64                        // K elements per SMEM chunk
#define NCHUNK (FD / KCH)               // 4
#define TILE_EL (MD * KCH)              // 8192 halfs per tile
#define TILE_BYTES (TILE_EL * 2)        // 16384
#define BUF_BYTES (3 * TILE_BYTES)      // Ahi, Bhi, Blo
#define SMEM_TOTAL (2 * BUF_BYTES)      // 98304 (double buffered)

// Split-precision K-major scratch: [t*64+b][chunk][m][k_local], fp16
__device__ __half g_hi[2 * BSZ * NCHUNK * TILE_EL];   // 8 MB
__device__ __half g_lo[2 * BSZ * NCHUNK * TILE_EL];   // 8 MB

__device__ __forceinline__ uint32_t smem_u32(const void* p) {
    uint32_t a;
    asm("{ .reg .u64 t; cvta.to.shared.u64 t, %1; cvt.u32.u64 %0, t; }"
        : "=r"(a) : "l"(p));
    return a;
}

#define SWZ(o) ((o) ^ (((o) >> 3) & 0x70))

// ---------------- Kernel 1: fp32 -> fp16 hi/lo split + transpose ----------------
__global__ __launch_bounds__(256)
void split_transpose_kernel(const float* __restrict__ m1,
                            const float* __restrict__ m2)
{
    __shared__ float tile[KCH][MD + 1];
    const int tb = blockIdx.x;              // 0..127 = t*64 + b
    const int t  = tb >> 6;
    const int b  = tb & 63;
    const float* src = (t ? m2 : m1) + (size_t)b * FD * MD;
    const int tid = threadIdx.x;

    for (int kc = 0; kc < NCHUNK; kc++) {
        const float* s = src + (size_t)kc * KCH * MD;
#pragma unroll
        for (int it = 0; it < 8; it++) {
            int i4 = it * 256 + tid;               // 0..2047 float4s
            int f  = i4 >> 5;
            int m4 = (i4 & 31) * 4;
            float4 v = *(const float4*)(s + f * MD + m4);
            tile[f][m4]     = v.x;
            tile[f][m4 + 1] = v.y;
            tile[f][m4 + 2] = v.z;
            tile[f][m4 + 3] = v.w;
        }
        __syncthreads();
        size_t base = ((size_t)tb * NCHUNK + kc) * TILE_EL;
#pragma unroll
        for (int it = 0; it < 4; it++) {
            int idx = it * 256 + tid;              // [128 m][8 kgroups]
            int m  = idx >> 3;
            int kl = (idx & 7) * 8;
            __half hv[8], lv[8];
#pragma unroll
            for (int j = 0; j < 8; j++) {
                float x = tile[kl + j][m];
                __half h = __float2half_rn(x);
                hv[j] = h;
                lv[j] = __float2half_rn(x - __half2float(h));
            }
            *(uint4*)(&g_hi[base + (size_t)m * KCH + kl]) = *(const uint4*)hv;
            *(uint4*)(&g_lo[base + (size_t)m * KCH + kl]) = *(const uint4*)lv;
        }
        __syncthreads();
    }
}

// ---------------- Kernel 2: fp16 HMMA Gram + fused histogram ----------------
#define MMA_F16(d, A, B)                                                       \
    asm volatile("mma.sync.aligned.m16n8k16.row.col.f32.f16.f16.f32 "          \
                 "{%0,%1,%2,%3},{%4,%5,%6,%7},{%8,%9},{%0,%1,%2,%3};"          \
                 : "+f"(d[0]), "+f"(d[1]), "+f"(d[2]), "+f"(d[3])              \
                 : "r"(A[0]), "r"(A[1]), "r"(A[2]), "r"(A[3]),                 \
                   "r"(B[0]), "r"(B[1]))

#define LDSM_X4(r, addr)                                                       \
    asm volatile("ldmatrix.sync.aligned.m8n8.x4.shared.b16 {%0,%1,%2,%3},[%4];"\
                 : "=r"(r[0]), "=r"(r[1]), "=r"(r[2]), "=r"(r[3])              \
                 : "r"(addr))

// stage one chunk (Ahi, Bhi, Blo) into a smem buffer via cp.async
__device__ __forceinline__ void load_chunk(uint32_t buf_base,
                                           const __half* gA_hi,
                                           const __half* gB_hi,
                                           const __half* gB_lo,
                                           int tid)
{
    const __half* gs[3] = { gA_hi, gB_hi, gB_lo };
#pragma unroll
    for (int T = 0; T < 3; T++) {
#pragma unroll
        for (int it = 0; it < 4; it++) {
            int idx = it * 256 + tid;           // 1024 16B-chunks per tile
            int m  = idx >> 3;
            int kg = idx & 7;
            uint32_t soff = (uint32_t)T * TILE_BYTES + SWZ((uint32_t)(m * 128 + kg * 16));
            const void* ga = gs[T] + (size_t)m * KCH + kg * 8;
            asm volatile("cp.async.cg.shared.global [%0], [%1], 16;"
                         :: "r"(buf_base + soff), "l"(ga));
        }
    }
    asm volatile("cp.async.commit_group;" ::: "memory");
}

__global__ __launch_bounds__(256, 2)
void pair_hist_mma_kernel(float* __restrict__ out)
{
    extern __shared__ __align__(16) char smem[];
    const uint32_t sb = smem_u32(smem);

    __shared__ float s_bins[NBINS - 1];
    __shared__ float s_wmn[8], s_wmx[8];
    __shared__ float s_mm[2];

    const int tid  = threadIdx.x;
    const int wid  = tid >> 5;
    const int lane = tid & 31;
    const int wm   = wid & 1;     // 2 row-groups of 64
    const int wn   = wid >> 1;    // 4 col-groups of 32

    if (tid < NBINS - 1) s_bins[tid] = 0.0f;

    // unrank pair
    const int bid = blockIdx.x;
    const int t   = (bid >= NPAIR) ? 1 : 0;
    int p = bid - t * NPAIR;
    int a = 0;
    while (p >= BSZ - a) { p -= BSZ - a; a++; }
    const int b = a + p;

    const size_t tA = (size_t)(t * BSZ + a) * NCHUNK * TILE_EL;
    const size_t tB = (size_t)(t * BSZ + b) * NCHUNK * TILE_EL;

    float acc[4][4][4];
#pragma unroll
    for (int i = 0; i < 4; i++)
#pragma unroll
        for (int j = 0; j < 4; j++)
#pragma unroll
            for (int q = 0; q < 4; q++) acc[i][j][q] = 0.0f;

    // ldmatrix lane addressing
    const int a_row  = wm * 64 + (lane & 15);
    const int a_koff = (lane >> 4) * 16;
    const int b_row  = wn * 32 + ((lane >> 4) << 3) + (lane & 7);
    const int b_koff = ((lane >> 3) & 1) * 16;

    // prologue: chunks 0 and 1 in flight
    load_chunk(sb,             g_hi + tA,           g_hi + tB,           g_lo + tB,           tid);
    load_chunk(sb + BUF_BYTES, g_hi + tA + TILE_EL, g_hi + tB + TILE_EL, g_lo + tB + TILE_EL, tid);

    for (int c = 0; c < NCHUNK; c++) {
        if (c < NCHUNK - 1)
            asm volatile("cp.async.wait_group 1;" ::: "memory");
        else
            asm volatile("cp.async.wait_group 0;" ::: "memory");
        __syncthreads();

        const uint32_t bufb = sb + (uint32_t)(c & 1) * BUF_BYTES;
#pragma unroll
        for (int ks = 0; ks < 4; ks++) {       // 4 k16-steps within KCH=64
            uint32_t ahi[4][4];
#pragma unroll
            for (int mt = 0; mt < 4; mt++) {
                uint32_t off = SWZ((uint32_t)((a_row + mt * 16) * 128 + ks * 32 + a_koff));
                LDSM_X4(ahi[mt], bufb + off);
            }
            uint32_t bhi[4][2], blo[4][2];
#pragma unroll
            for (int np = 0; np < 2; np++) {
                uint32_t off = SWZ((uint32_t)((b_row + np * 16) * 128 + ks * 32 + b_koff));
                uint32_t rh[4], rl[4];
                LDSM_X4(rh, bufb + TILE_BYTES + off);
                LDSM_X4(rl, bufb + 2 * TILE_BYTES + off);
                bhi[np * 2][0] = rh[0]; bhi[np * 2][1] = rh[1];
                bhi[np * 2 + 1][0] = rh[2]; bhi[np * 2 + 1][1] = rh[3];
                blo[np * 2][0] = rl[0]; blo[np * 2][1] = rl[1];
                blo[np * 2 + 1][0] = rl[2]; blo[np * 2 + 1][1] = rl[3];
            }
#pragma unroll
            for (int mt = 0; mt < 4; mt++)
#pragma unroll
                for (int nt = 0; nt < 4; nt++) {
                    MMA_F16(acc[mt][nt], ahi[mt], bhi[nt]);
                    MMA_F16(acc[mt][nt], ahi[mt], blo[nt]);
                }
        }

        if (c + 2 < NCHUNK) {
            __syncthreads();                    // all warps done reading this buffer
            size_t co = (size_t)(c + 2) * TILE_EL;
            load_chunk(bufb, g_hi + tA + co, g_hi + tB + co, g_lo + tB + co, tid);
        }
    }

    // ---- epilogue: histogram over the 64 per-thread accumulators ----
    float* av = &acc[0][0][0];

    float mn = av[0], mx = av[0];
#pragma unroll
    for (int i = 1; i < 64; i++) {
        mn = fminf(mn, av[i]);
        mx = fmaxf(mx, av[i]);
    }
#pragma unroll
    for (int o = 16; o > 0; o >>= 1) {
        mn = fminf(mn, __shfl_xor_sync(0xffffffffu, mn, o));
        mx = fmaxf(mx, __shfl_xor_sync(0xffffffffu, mx, o));
    }
    if (lane == 0) { s_wmn[wid] = mn; s_wmx[wid] = mx; }
    __syncthreads();
    if (tid == 0) {
        float m0 = s_wmn[0], m1v = s_wmx[0];
#pragma unroll
        for (int w = 1; w < 8; w++) {
            m0  = fminf(m0,  s_wmn[w]);
            m1v = fmaxf(m1v, s_wmx[w]);
        }
        s_mm[0] = m0; s_mm[1] = m1v;
    }
    __syncthreads();
    mn = s_mm[0]; mx = s_mm[1];

    const float denom = (mx > mn) ? (mx - mn) : 1.0f;
    const float scale = 8.0f / denom;
    const float off   = -mn * scale;
    float cge[7] = {0, 0, 0, 0, 0, 0, 0};
#pragma unroll
    for (int i = 0; i < 64; i++) {
        float y = fmaf(av[i], scale, off);
#pragma unroll
        for (int q = 0; q < 7; q++)
            cge[q] += (y >= (float)(q + 1)) ? 1.0f : 0.0f;
    }
#pragma unroll
    for (int q = 0; q < 7; q++) {
#pragma unroll
        for (int o = 16; o > 0; o >>= 1)
            cge[q] += __shfl_xor_sync(0xffffffffu, cge[q], o);
        if (lane == 0) atomicAdd(&s_bins[q], cge[q]);
    }
    __syncthreads();

    if (tid == 0) {
        float C[9];
        C[0] = (float)(MD * MD);
        C[8] = 0.0f;
#pragma unroll
        for (int q = 1; q < 8; q++) C[q] = s_bins[q - 1];
        float h[8], nrm = 0.0f;
#pragma unroll
        for (int q = 0; q < 8; q++) {
            h[q] = C[q] - C[q + 1];
            nrm += h[q] * h[q];
        }
        const float inv = 1.0f / sqrtf(nrm);
        const int r1 = a * BSZ + b;
        const int r2 = b * BSZ + a;
        float* o1 = out + (size_t)r1 * 16 + t * 8;
        float* o2 = out + (size_t)r2 * 16 + t * 8;
#pragma unroll
        for (int q = 0; q < 8; q++) {
            float v = h[q] * inv;
            o1[q] = v;
            o2[q] = v;
        }
    }
}

// ---------------- launch ----------------
extern "C" void kernel_launch(void* const* d_in, const int* in_sizes, int n_in,
                              void* d_out, int out_size)
{
    const float* m1 = (const float*)d_in[0];
    const float* m2 = (const float*)d_in[1];
    float* out = (float*)d_out;

    cudaFuncSetAttribute(pair_hist_mma_kernel,
                         cudaFuncAttributeMaxDynamicSharedMemorySize, SMEM_TOTAL);

    split_transpose_kernel<<<2 * BSZ, 256>>>(m1, m2);
    pair_hist_mma_kernel<<<2 * NPAIR, 256, SMEM_TOTAL>>>(out);
}